// round 13
// baseline (speedup 1.0000x reference)
#include <cuda_runtime.h>
#include <cuda_fp16.h>
#include <cstdint>

#define BB 16
#define CC 128
#define OO 128
#define HH 112
#define WW 112
#define HWSZ (HH*WW)        // 12544
#define TH 28

#define WPITCH 136                       // W row pitch (elems) -> 272 B
#define WTAP (128 * WPITCH * 2)          // one fp16 tap = 34816 B
#define XP 136                           // X fp16 row pitch (elems) -> 272 B
#define XBYTES (128 * XP * 2)            // 34816 B
#define NT 128                           // pixels per pass1 tile

// Scratch: G[k][b][o][h][w] in fp16  (154 MB)
__device__ __align__(128) __half g_G[3 * BB * OO * HWSZ];
// Prepacked fp16 weights: [tap][o=128][WPITCH] (pad cols zeroed)
__device__ __align__(128) unsigned short g_Wt[3 * 128 * WPITCH];

// ---------------------------------------------------------------------------
// Helpers
// ---------------------------------------------------------------------------
__device__ __forceinline__ uint32_t smem_u32(const void* p) {
    uint32_t a;
    asm("{ .reg .u64 t; cvta.to.shared.u64 t, %1; cvt.u32.u64 %0, t; }" : "=r"(a) : "l"(p));
    return a;
}
__device__ __forceinline__ void cp_async16(uint32_t dst, const void* src) {
    asm volatile("cp.async.ca.shared.global [%0], [%1], 16;" :: "r"(dst), "l"(src));
}
#define CP_COMMIT() asm volatile("cp.async.commit_group;" ::: "memory")
#define CP_WAIT0()  asm volatile("cp.async.wait_group 0;" ::: "memory")

__device__ __forceinline__ void ldmat_x4(uint32_t* r, uint32_t addr) {
    asm volatile("ldmatrix.sync.aligned.m8n8.x4.shared.b16 {%0,%1,%2,%3}, [%4];"
                 : "=r"(r[0]), "=r"(r[1]), "=r"(r[2]), "=r"(r[3]) : "r"(addr));
}
__device__ __forceinline__ void ldmat_x4_t(uint32_t* r, uint32_t addr) {
    asm volatile("ldmatrix.sync.aligned.m8n8.x4.trans.shared.b16 {%0,%1,%2,%3}, [%4];"
                 : "=r"(r[0]), "=r"(r[1]), "=r"(r[2]), "=r"(r[3]) : "r"(addr));
}
// fp16 inputs, fp32 accumulate
__device__ __forceinline__ void mma16816h(float* d, const uint32_t* a,
                                          uint32_t b0, uint32_t b1) {
    asm volatile("mma.sync.aligned.m16n8k16.row.col.f32.f16.f16.f32 "
                 "{%0,%1,%2,%3}, {%4,%5,%6,%7}, {%8,%9}, {%0,%1,%2,%3};"
                 : "+f"(d[0]), "+f"(d[1]), "+f"(d[2]), "+f"(d[3])
                 : "r"(a[0]), "r"(a[1]), "r"(a[2]), "r"(a[3]), "r"(b0), "r"(b1));
}
__device__ __forceinline__ uint32_t packh2(float a, float b) {
    __half2 h = __floats2half2_rn(a, b);
    return *(uint32_t*)&h;
}

// ---------------------------------------------------------------------------
// Weight prep (single kernel): w[o][c][k] -> fp16, layout [tap][o][WPITCH].
// ---------------------------------------------------------------------------
__global__ void prep_w(const float* __restrict__ w) {
    int i = blockIdx.x * 256 + threadIdx.x;
    if (i >= 3 * 128 * WPITCH) return;
    int k = i / (128 * WPITCH);
    int r = i % (128 * WPITCH);
    int o = r / WPITCH;
    int c = r % WPITCH;
    unsigned short hv = 0;
    if (c < 128)
        hv = __half_as_ushort(__float2half_rn(w[(o * 128 + c) * 3 + k]));
    g_Wt[k * 128 * WPITCH + o * WPITCH + c] = hv;
}

// ---------------------------------------------------------------------------
// Pass1 building blocks
// ---------------------------------------------------------------------------
// Convert 64 c-rows of fp32 X (tight [c][128] in staging smem) into fp16 Xs
// with the R12 column permutation: px-quad q -> col base
//   c0(q) = 64*(q>>4) + 16*(q&3) + 2*((q>>2)&3)
__device__ __forceinline__ void convert_half(char* xs, const char* stg,
                                             int tid, int cbase) {
    #pragma unroll
    for (int i = 0; i < 8; i++) {
        int idx = i * 256 + tid;
        int c = idx >> 5;
        int q = idx & 31;
        float4 v = *(const float4*)(stg + c * 512 + q * 16);
        uint32_t p0 = packh2(v.x, v.y);
        uint32_t p1 = packh2(v.z, v.w);
        int c0 = 64 * (q >> 4) + 16 * (q & 3) + 2 * ((q >> 2) & 3);
        int row = cbase + c;
        *(uint32_t*)(xs + row * (XP * 2) + c0 * 2)       = p0;
        *(uint32_t*)(xs + row * (XP * 2) + (c0 + 8) * 2) = p1;
    }
}

// cp.async one W tap (2176 float4) into dst.
__device__ __forceinline__ void fetch_w(uint32_t dst, int k, int tid) {
    const char* src = (const char*)g_Wt + (size_t)k * WTAP;
    #pragma unroll
    for (int t = 0; t < 9; t++) {
        int i = t * 256 + tid;
        if (i < 2176) cp_async16(dst + i * 16, src + (size_t)i * 16);
    }
}
// cp.async half of X fp32 (64 rows x 128 px = 2048 float4) into staging.
__device__ __forceinline__ void fetch_xhalf(uint32_t dst, const float* xb,
                                            int cbase, int tid) {
    #pragma unroll
    for (int t = 0; t < 8; t++) {
        int i = t * 256 + tid;
        int c = i >> 5;
        int q = i & 31;
        cp_async16(dst + i * 16, xb + (size_t)(cbase + c) * HWSZ + q * 4);
    }
}

// MMA over ks in [KS0, KS1).
template <int KS0, int KS1>
__device__ __forceinline__ void mma_block(float (&acc)[2][8][4],
    uint32_t wb, uint32_t xs_u, int m0, int n0w,
    int a_row, int a_col, int b_row, int b_col)
{
    #pragma unroll
    for (int ks = KS0; ks < KS1; ks++) {
        uint32_t a[2][4];
        #pragma unroll
        for (int mt = 0; mt < 2; mt++)
            ldmat_x4(a[mt], wb + (m0 + mt * 16 + a_row) * (WPITCH * 2)
                              + (ks * 16 + a_col) * 2);
        #pragma unroll
        for (int nt2 = 0; nt2 < 4; nt2++) {
            uint32_t bbf[4];
            ldmat_x4_t(bbf, xs_u + (ks * 16 + b_row) * (XP * 2)
                             + (n0w + nt2 * 16 + b_col) * 2);
            #pragma unroll
            for (int mt = 0; mt < 2; mt++) {
                #pragma unroll
                for (int j = 0; j < 2; j++)
                    mma16816h(acc[mt][nt2 * 2 + j], a[mt],
                              bbf[j * 2], bbf[j * 2 + 1]);
            }
        }
    }
}

__device__ __forceinline__ void zero_acc(float (&acc)[2][8][4]) {
    #pragma unroll
    for (int i = 0; i < 2; i++)
        #pragma unroll
        for (int j = 0; j < 8; j++)
            #pragma unroll
            for (int q = 0; q < 4; q++) acc[i][j][q] = 0.0f;
}

// Epilogue: lane's 16 contiguous px per row -> 2x STG.128 per row.
__device__ __forceinline__ void epilogue(float (&acc)[2][8][4], __half* gk,
                                         int m0, int n0w, int gid, int tig) {
    const int pxb = n0w + tig * 16;
    #pragma unroll
    for (int mt = 0; mt < 2; mt++) {
        uint4 ra0, ra1, rb0, rb1;
        ra0.x = packh2(acc[mt][0][0], acc[mt][0][1]);
        ra0.y = packh2(acc[mt][1][0], acc[mt][1][1]);
        ra0.z = packh2(acc[mt][2][0], acc[mt][2][1]);
        ra0.w = packh2(acc[mt][3][0], acc[mt][3][1]);
        ra1.x = packh2(acc[mt][4][0], acc[mt][4][1]);
        ra1.y = packh2(acc[mt][5][0], acc[mt][5][1]);
        ra1.z = packh2(acc[mt][6][0], acc[mt][6][1]);
        ra1.w = packh2(acc[mt][7][0], acc[mt][7][1]);
        rb0.x = packh2(acc[mt][0][2], acc[mt][0][3]);
        rb0.y = packh2(acc[mt][1][2], acc[mt][1][3]);
        rb0.z = packh2(acc[mt][2][2], acc[mt][2][3]);
        rb0.w = packh2(acc[mt][3][2], acc[mt][3][3]);
        rb1.x = packh2(acc[mt][4][2], acc[mt][4][3]);
        rb1.y = packh2(acc[mt][5][2], acc[mt][5][3]);
        rb1.z = packh2(acc[mt][6][2], acc[mt][6][3]);
        rb1.w = packh2(acc[mt][7][2], acc[mt][7][3]);
        int rowA = m0 + mt * 16 + gid;
        int rowB = rowA + 8;
        *(uint4*)(gk + (size_t)rowA * HWSZ + pxb)     = ra0;
        *(uint4*)(gk + (size_t)rowA * HWSZ + pxb + 8) = ra1;
        *(uint4*)(gk + (size_t)rowB * HWSZ + pxb)     = rb0;
        *(uint4*)(gk + (size_t)rowB * HWSZ + pxb + 8) = rb1;
    }
}

// ---------------------------------------------------------------------------
// Pass 1 (cp.async-pipelined X staging through the spare W buffer).
// Timeline: {W0,Xa}->async; cvt a; Xb->async; tap0 ks0-3; cvt b; W1->async;
// tap0 ks4-7 + epi0; W2->async; tap1 + epi1; tap2 + epi2.
// smem: Xs 34816 + WB0 34816 + WB1 34816 = 104448 -> 2 CTAs/SM.
// ---------------------------------------------------------------------------
__global__ __launch_bounds__(256, 2) void pass1_mma(const float* __restrict__ x) {
    extern __shared__ __align__(16) char dsm[];
    char* xs  = dsm;                     // X fp16, permuted cols
    char* wb0 = dsm + XBYTES;            // W buffer 0
    char* wb1 = dsm + XBYTES + WTAP;     // W buffer 1 / X fp32 staging

    const int tid = threadIdx.x;
    const int wrp = tid >> 5;
    const int lid = tid & 31;
    const int gid = lid >> 2;
    const int tig = lid & 3;
    const int n0 = blockIdx.x * NT;
    const int b  = blockIdx.y;

    const uint32_t xs_u  = smem_u32(xs);
    const uint32_t wb0_u = smem_u32(wb0);
    const uint32_t wb1_u = smem_u32(wb1);

    const float* xb = x + (size_t)b * CC * HWSZ + n0;

    // S0: W0 + X half a (c0..63) in one async group.
    fetch_w(wb0_u, 0, tid);
    fetch_xhalf(wb1_u, xb, 0, tid);
    CP_COMMIT();
    CP_WAIT0();
    __syncthreads();

    // Convert half a into Xs rows 0..63.
    convert_half(xs, wb1, tid, 0);
    __syncthreads();

    // Issue X half b while tap0 (ks0-3) computes on half a.
    fetch_xhalf(wb1_u, xb, 64, tid);
    CP_COMMIT();

    const int m0  = (wrp & 3) * 32;
    const int n0w = (wrp >> 2) * 64;
    const int mi = lid >> 3;
    const int mr = lid & 7;
    const int a_row = (mi & 1) * 8 + mr;
    const int a_col = (mi >> 1) * 8;
    const int b_row = (mi & 1) * 8 + mr;
    const int b_col = (mi >> 1) * 8;

    float acc[2][8][4];
    zero_acc(acc);
    mma_block<0, 4>(acc, wb0_u, xs_u, m0, n0w, a_row, a_col, b_row, b_col);

    CP_WAIT0();
    __syncthreads();
    convert_half(xs, wb1, tid, 64);
    __syncthreads();

    // W1 into wb1 (staging no longer needed); tap0 ks4-7 overlaps.
    fetch_w(wb1_u, 1, tid);
    CP_COMMIT();

    mma_block<4, 8>(acc, wb0_u, xs_u, m0, n0w, a_row, a_col, b_row, b_col);
    epilogue(acc, g_G + ((size_t)(0 * BB + b) * OO) * HWSZ + n0, m0, n0w, gid, tig);

    CP_WAIT0();
    __syncthreads();          // W1 ready; all warps done with wb0

    // W2 into wb0; tap1 from wb1 overlaps.
    fetch_w(wb0_u, 2, tid);
    CP_COMMIT();

    zero_acc(acc);
    mma_block<0, 8>(acc, wb1_u, xs_u, m0, n0w, a_row, a_col, b_row, b_col);
    epilogue(acc, g_G + ((size_t)(1 * BB + b) * OO) * HWSZ + n0, m0, n0w, gid, tig);

    CP_WAIT0();
    __syncthreads();          // W2 ready; all warps done with wb1

    zero_acc(acc);
    mma_block<0, 8>(acc, wb0_u, xs_u, m0, n0w, a_row, a_col, b_row, b_col);
    epilogue(acc, g_G + ((size_t)(2 * BB + b) * OO) * HWSZ + n0, m0, n0w, gid, tig);
}

// ---------------------------------------------------------------------------
// Pass 2 (unchanged R12): lane-per-quad, shuffle halos, 8 dirs unrolled,
// streaming loads/stores.
// ---------------------------------------------------------------------------
__global__ __launch_bounds__(256, 3) void pass2_shift(float* __restrict__ out) {
    const int bid = blockIdx.x;
    const int ht = bid & 3;
    const int bo = bid >> 2;
    const int o  = bo & 127;
    const int b  = bo >> 7;
    const int h0 = ht * TH;

    __shared__ __align__(16) float Gs[3][TH + 2][116];

    const int tid = threadIdx.x;

    for (int idx = tid; idx < 3 * (TH + 2) * 28; idx += 256) {
        int k   = idx / ((TH + 2) * 28);
        int r   = idx % ((TH + 2) * 28);
        int row = r / 28;
        int q   = r % 28;
        int gh  = h0 - 1 + row;
        float4 v = make_float4(0.f, 0.f, 0.f, 0.f);
        if (gh >= 0 && gh < HH) {
            const __half* gsrc = g_G +
                ((size_t)((k * BB + b) * OO + o)) * HWSZ + gh * WW + q * 4;
            uint2 raw = __ldcs((const uint2*)gsrc);
            __half2 p01 = *reinterpret_cast<__half2*>(&raw.x);
            __half2 p23 = *reinterpret_cast<__half2*>(&raw.y);
            float2 f01 = __half22float2(p01);
            float2 f23 = __half22float2(p23);
            v = make_float4(f01.x, f01.y, f23.x, f23.y);
        }
        *(float4*)&Gs[k][row][q * 4] = v;
    }
    __syncthreads();

    const int lane = tid & 31;
    const int wrp  = tid >> 5;
    const bool act = lane < 28;
    const int q    = act ? lane : 27;
    const bool nzl = (lane > 0);
    const bool nzr = (lane < 27);

    float* ob = out + ((size_t)(b * OO + o) * 8) * HWSZ + h0 * WW + q * 4;

    #pragma unroll
    for (int i = 0; i < 4; i++) {
        const int hl = wrp + i * 8;
        if (hl >= TH) break;
        const int r = hl + 1;

        float4 A  = *(float4*)&Gs[1][r    ][q * 4];
        float4 B0 = *(float4*)&Gs[0][r - 1][q * 4];
        float4 B1 = *(float4*)&Gs[0][r    ][q * 4];
        float4 B2 = *(float4*)&Gs[0][r + 1][q * 4];
        float4 C0 = *(float4*)&Gs[2][r - 1][q * 4];
        float4 C1 = *(float4*)&Gs[2][r    ][q * 4];
        float4 C2 = *(float4*)&Gs[2][r + 1][q * 4];

        float B0l = __shfl_up_sync(0xffffffffu, B0.w, 1);  B0l = nzl ? B0l : 0.f;
        float B1l = __shfl_up_sync(0xffffffffu, B1.w, 1);  B1l = nzl ? B1l : 0.f;
        float B2l = __shfl_up_sync(0xffffffffu, B2.w, 1);  B2l = nzl ? B2l : 0.f;
        float C0l = __shfl_up_sync(0xffffffffu, C0.w, 1);  C0l = nzl ? C0l : 0.f;
        float C1l = __shfl_up_sync(0xffffffffu, C1.w, 1);  C1l = nzl ? C1l : 0.f;
        float C2l = __shfl_up_sync(0xffffffffu, C2.w, 1);  C2l = nzl ? C2l : 0.f;
        float B0r = __shfl_down_sync(0xffffffffu, B0.x, 1); B0r = nzr ? B0r : 0.f;
        float B1r = __shfl_down_sync(0xffffffffu, B1.x, 1); B1r = nzr ? B1r : 0.f;
        float B2r = __shfl_down_sync(0xffffffffu, B2.x, 1); B2r = nzr ? B2r : 0.f;
        float C0r = __shfl_down_sync(0xffffffffu, C0.x, 1); C0r = nzr ? C0r : 0.f;
        float C1r = __shfl_down_sync(0xffffffffu, C1.x, 1); C1r = nzr ? C1r : 0.f;
        float C2r = __shfl_down_sync(0xffffffffu, C2.x, 1); C2r = nzr ? C2r : 0.f;

        if (act) {
            float* op = ob + hl * WW;
            float4 res;
            res.x = A.x + B1l  + C1.y; res.y = A.y + B1.x + C1.z;
            res.z = A.z + B1.y + C1.w; res.w = A.w + B1.z + C1r;
            __stcs((float4*)(op + 0 * HWSZ), res);
            res.x = A.x + B0l  + C2.y; res.y = A.y + B0.x + C2.z;
            res.z = A.z + B0.y + C2.w; res.w = A.w + B0.z + C2r;
            __stcs((float4*)(op + 1 * HWSZ), res);
            res.x = A.x + B0.x + C2.x; res.y = A.y + B0.y + C2.y;
            res.z = A.z + B0.z + C2.z; res.w = A.w + B0.w + C2.w;
            __stcs((float4*)(op + 2 * HWSZ), res);
            res.x = A.x + B0.y + C2l;  res.y = A.y + B0.z + C2.x;
            res.z = A.z + B0.w + C2.y; res.w = A.w + B0r  + C2.z;
            __stcs((float4*)(op + 3 * HWSZ), res);
            res.x = A.x + B1.y + C1l;  res.y = A.y + B1.z + C1.x;
            res.z = A.z + B1.w + C1.y; res.w = A.w + B1r  + C1.z;
            __stcs((float4*)(op + 4 * HWSZ), res);
            res.x = A.x + B2.y + C0l;  res.y = A.y + B2.z + C0.x;
            res.z = A.z + B2.w + C0.y; res.w = A.w + B2r  + C0.z;
            __stcs((float4*)(op + 5 * HWSZ), res);
            res.x = A.x + B2.x + C0.x; res.y = A.y + B2.y + C0.y;
            res.z = A.z + B2.z + C0.z; res.w = A.w + B2.w + C0.w;
            __stcs((float4*)(op + 6 * HWSZ), res);
            res.x = A.x + B2l  + C0.y; res.y = A.y + B2.x + C0.z;
            res.z = A.z + B2.y + C0.w; res.w = A.w + B2.z + C0r;
            __stcs((float4*)(op + 7 * HWSZ), res);
        }
    }
}

// ---------------------------------------------------------------------------
extern "C" void kernel_launch(void* const* d_in, const int* in_sizes, int n_in,
                              void* d_out, int out_size) {
    const float* x = (const float*)d_in[0];       // [16,128,112,112]
    const float* w = (const float*)d_in[1];       // [128,128,3]
    float* out = (float*)d_out;                   // [16,128,8,112,112]

    prep_w<<<(3 * 128 * WPITCH + 255) / 256, 256>>>(w);

    const int dyn_smem = XBYTES + 2 * WTAP;       // 104448 B
    cudaFuncSetAttribute(pass1_mma,
                         cudaFuncAttributeMaxDynamicSharedMemorySize, dyn_smem);
    dim3 g1(HWSZ / NT, BB);                       // (98, 16)
    pass1_mma<<<g1, 256, dyn_smem>>>(x);

    pass2_shift<<<BB * OO * 4, 256>>>(out);
}

// round 14
// speedup vs baseline: 1.0106x; 1.0106x over previous
#include <cuda_runtime.h>
#include <cuda_fp16.h>
#include <cstdint>

#define BB 16
#define CC 128
#define OO 128
#define HH 112
#define WW 112
#define HWSZ (HH*WW)        // 12544
#define TH 28

#define WPITCH 136                       // W row pitch (elems) -> 272 B
#define WTAP (128 * WPITCH * 2)          // one fp16 tap = 34816 B
#define XP 136                           // X fp16 row pitch (elems) -> 272 B
#define XBYTES (128 * XP * 2)            // 34816 B
#define NT 128                           // pixels per pass1 tile

// Scratch: G[k][b][o][h][w] in fp16  (154 MB)
__device__ __align__(128) __half g_G[3 * BB * OO * HWSZ];
// Prepacked fp16 weights: [tap][o=128][WPITCH] (pad cols zeroed)
__device__ __align__(128) unsigned short g_Wt[3 * 128 * WPITCH];

// ---------------------------------------------------------------------------
// Helpers
// ---------------------------------------------------------------------------
__device__ __forceinline__ uint32_t smem_u32(const void* p) {
    uint32_t a;
    asm("{ .reg .u64 t; cvta.to.shared.u64 t, %1; cvt.u32.u64 %0, t; }" : "=r"(a) : "l"(p));
    return a;
}
__device__ __forceinline__ void cp_async16(uint32_t dst, const void* src) {
    asm volatile("cp.async.ca.shared.global [%0], [%1], 16;" :: "r"(dst), "l"(src));
}
#define CP_COMMIT() asm volatile("cp.async.commit_group;" ::: "memory")
#define CP_WAIT0()  asm volatile("cp.async.wait_group 0;" ::: "memory")

__device__ __forceinline__ void ldmat_x4(uint32_t* r, uint32_t addr) {
    asm volatile("ldmatrix.sync.aligned.m8n8.x4.shared.b16 {%0,%1,%2,%3}, [%4];"
                 : "=r"(r[0]), "=r"(r[1]), "=r"(r[2]), "=r"(r[3]) : "r"(addr));
}
__device__ __forceinline__ void ldmat_x4_t(uint32_t* r, uint32_t addr) {
    asm volatile("ldmatrix.sync.aligned.m8n8.x4.trans.shared.b16 {%0,%1,%2,%3}, [%4];"
                 : "=r"(r[0]), "=r"(r[1]), "=r"(r[2]), "=r"(r[3]) : "r"(addr));
}
// fp16 inputs, fp32 accumulate
__device__ __forceinline__ void mma16816h(float* d, const uint32_t* a,
                                          uint32_t b0, uint32_t b1) {
    asm volatile("mma.sync.aligned.m16n8k16.row.col.f32.f16.f16.f32 "
                 "{%0,%1,%2,%3}, {%4,%5,%6,%7}, {%8,%9}, {%0,%1,%2,%3};"
                 : "+f"(d[0]), "+f"(d[1]), "+f"(d[2]), "+f"(d[3])
                 : "r"(a[0]), "r"(a[1]), "r"(a[2]), "r"(a[3]), "r"(b0), "r"(b1));
}
__device__ __forceinline__ uint32_t packh2(float a, float b) {
    __half2 h = __floats2half2_rn(a, b);
    return *(uint32_t*)&h;
}

// ---------------------------------------------------------------------------
// Weight prep (single kernel): w[o][c][k] -> fp16, layout [tap][o][WPITCH].
// ---------------------------------------------------------------------------
__global__ void prep_w(const float* __restrict__ w) {
    int i = blockIdx.x * 256 + threadIdx.x;
    if (i >= 3 * 128 * WPITCH) return;
    int k = i / (128 * WPITCH);
    int r = i % (128 * WPITCH);
    int o = r / WPITCH;
    int c = r % WPITCH;
    unsigned short hv = 0;
    if (c < 128)
        hv = __half_as_ushort(__float2half_rn(w[(o * 128 + c) * 3 + k]));
    g_Wt[k * 128 * WPITCH + o * WPITCH + c] = hv;
}

// ---------------------------------------------------------------------------
// Pass 1 (R12 version: fp16 single-product + permuted X cols for STG.128
// epilogue; direct LDG->cvt->STS X load; W double-buffered via cp.async).
// X smem column permutation (within each 64-px chunk):
//   col(px) = chunk*64 + ((px&15)>>1)*8 + ((px>>4)&3)*2 + (px&1)
// => lane (tig) accumulates 16 CONTIGUOUS px per row -> 2x STG.128.
// CTA: 128o x 128px, 3 taps; 8 warps (4m x 2n), warp tile 32o x 64px.
// smem: X 34816 + W double-buffer 2x34816 = 104448 B -> 2 CTAs/SM.
// ---------------------------------------------------------------------------
__global__ __launch_bounds__(256, 2) void pass1_mma(const float* __restrict__ x) {
    extern __shared__ __align__(16) char dsm[];
    char* xs = dsm;                 // X fp16 [c][XP], permuted cols
    char* ws = dsm + XBYTES;        // W taps, 2 buffers

    const int tid = threadIdx.x;
    const int wrp = tid >> 5;
    const int lid = tid & 31;
    const int gid = lid >> 2;
    const int tig = lid & 3;
    const int n0 = blockIdx.x * NT;
    const int b  = blockIdx.y;

    const uint32_t xs_u = smem_u32(xs);
    const uint32_t ws_u = smem_u32(ws);

    // ---- Prefetch W tap0 into buffer 0 (34816 B = 2176 float4) ----
    {
        const char* src = (const char*)g_Wt;
        #pragma unroll
        for (int t = 0; t < 9; t++) {
            int i = t * 256 + tid;
            if (i < 2176) cp_async16(ws_u + i * 16, src + (size_t)i * 16);
        }
        CP_COMMIT();
    }

    // ---- Load X fp32, convert fp16, store at permuted columns ----
    const float* xb = x + (size_t)b * CC * HWSZ + n0;
    {
        const int c0 = 64 * (lid >> 4) + 16 * (lid & 3) + 2 * ((lid >> 2) & 3);
        #pragma unroll
        for (int it = 0; it < 16; it++) {
            int c = it * 8 + wrp;
            float4 v = *(const float4*)(xb + (size_t)c * HWSZ + lid * 4);
            uint32_t p0 = packh2(v.x, v.y);
            uint32_t p1 = packh2(v.z, v.w);
            *(uint32_t*)(xs + c * (XP * 2) + c0 * 2)       = p0;
            *(uint32_t*)(xs + c * (XP * 2) + (c0 + 8) * 2) = p1;
        }
    }

    CP_WAIT0();
    __syncthreads();

    // ---- Warp tiling: 4m x 2n, warp tile 32o x 64px ----
    const int m0  = (wrp & 3) * 32;
    const int n0w = (wrp >> 2) * 64;

    const int mi = lid >> 3;
    const int mr = lid & 7;
    const int a_row = (mi & 1) * 8 + mr;
    const int a_col = (mi >> 1) * 8;
    const int b_row = (mi & 1) * 8 + mr;
    const int b_col = (mi >> 1) * 8;

    float acc[2][8][4];

    #pragma unroll 1
    for (int k = 0; k < 3; k++) {
        // Prefetch next tap into other buffer (overlaps MMA + epilogue).
        if (k < 2) {
            uint32_t dstb = ws_u + ((k + 1) & 1) * WTAP;
            const char* src = (const char*)g_Wt + (size_t)(k + 1) * WTAP;
            #pragma unroll
            for (int t = 0; t < 9; t++) {
                int i = t * 256 + tid;
                if (i < 2176) cp_async16(dstb + i * 16, src + (size_t)i * 16);
            }
            CP_COMMIT();
        }

        #pragma unroll
        for (int i = 0; i < 2; i++)
            #pragma unroll
            for (int j = 0; j < 8; j++)
                #pragma unroll
                for (int q = 0; q < 4; q++) acc[i][j][q] = 0.0f;

        const uint32_t wb = ws_u + (k & 1) * WTAP;

        #pragma unroll
        for (int ks = 0; ks < 8; ks++) {
            uint32_t a[2][4];
            #pragma unroll
            for (int mt = 0; mt < 2; mt++)
                ldmat_x4(a[mt], wb + (m0 + mt * 16 + a_row) * (WPITCH * 2)
                                  + (ks * 16 + a_col) * 2);
            #pragma unroll
            for (int nt2 = 0; nt2 < 4; nt2++) {
                uint32_t bbf[4];
                ldmat_x4_t(bbf, xs_u + (ks * 16 + b_row) * (XP * 2)
                                 + (n0w + nt2 * 16 + b_col) * 2);
                #pragma unroll
                for (int mt = 0; mt < 2; mt++) {
                    #pragma unroll
                    for (int j = 0; j < 2; j++)
                        mma16816h(acc[mt][nt2 * 2 + j], a[mt],
                                  bbf[j * 2], bbf[j * 2 + 1]);
                }
            }
        }

        // ---- Epilogue: lane's 16 contiguous px per row -> STG.128 x2 ----
        __half* gk = g_G + ((size_t)(k * BB + b) * OO) * HWSZ + n0;
        const int pxb = n0w + tig * 16;
        #pragma unroll
        for (int mt = 0; mt < 2; mt++) {
            uint4 ra0, ra1, rb0, rb1;
            ra0.x = packh2(acc[mt][0][0], acc[mt][0][1]);
            ra0.y = packh2(acc[mt][1][0], acc[mt][1][1]);
            ra0.z = packh2(acc[mt][2][0], acc[mt][2][1]);
            ra0.w = packh2(acc[mt][3][0], acc[mt][3][1]);
            ra1.x = packh2(acc[mt][4][0], acc[mt][4][1]);
            ra1.y = packh2(acc[mt][5][0], acc[mt][5][1]);
            ra1.z = packh2(acc[mt][6][0], acc[mt][6][1]);
            ra1.w = packh2(acc[mt][7][0], acc[mt][7][1]);
            rb0.x = packh2(acc[mt][0][2], acc[mt][0][3]);
            rb0.y = packh2(acc[mt][1][2], acc[mt][1][3]);
            rb0.z = packh2(acc[mt][2][2], acc[mt][2][3]);
            rb0.w = packh2(acc[mt][3][2], acc[mt][3][3]);
            rb1.x = packh2(acc[mt][4][2], acc[mt][4][3]);
            rb1.y = packh2(acc[mt][5][2], acc[mt][5][3]);
            rb1.z = packh2(acc[mt][6][2], acc[mt][6][3]);
            rb1.w = packh2(acc[mt][7][2], acc[mt][7][3]);
            int rowA = m0 + mt * 16 + gid;
            int rowB = rowA + 8;
            *(uint4*)(gk + (size_t)rowA * HWSZ + pxb)     = ra0;
            *(uint4*)(gk + (size_t)rowA * HWSZ + pxb + 8) = ra1;
            *(uint4*)(gk + (size_t)rowB * HWSZ + pxb)     = rb0;
            *(uint4*)(gk + (size_t)rowB * HWSZ + pxb + 8) = rb1;
        }

        if (k < 2) {
            CP_WAIT0();
            __syncthreads();
        }
    }
}

// ---------------------------------------------------------------------------
// Pass 2 (unchanged R12): lane-per-quad, shuffle halos, 8 dirs unrolled,
// streaming loads/stores.
// ---------------------------------------------------------------------------
__global__ __launch_bounds__(256, 3) void pass2_shift(float* __restrict__ out) {
    const int bid = blockIdx.x;
    const int ht = bid & 3;
    const int bo = bid >> 2;
    const int o  = bo & 127;
    const int b  = bo >> 7;
    const int h0 = ht * TH;

    __shared__ __align__(16) float Gs[3][TH + 2][116];

    const int tid = threadIdx.x;

    for (int idx = tid; idx < 3 * (TH + 2) * 28; idx += 256) {
        int k   = idx / ((TH + 2) * 28);
        int r   = idx % ((TH + 2) * 28);
        int row = r / 28;
        int q   = r % 28;
        int gh  = h0 - 1 + row;
        float4 v = make_float4(0.f, 0.f, 0.f, 0.f);
        if (gh >= 0 && gh < HH) {
            const __half* gsrc = g_G +
                ((size_t)((k * BB + b) * OO + o)) * HWSZ + gh * WW + q * 4;
            uint2 raw = __ldcs((const uint2*)gsrc);
            __half2 p01 = *reinterpret_cast<__half2*>(&raw.x);
            __half2 p23 = *reinterpret_cast<__half2*>(&raw.y);
            float2 f01 = __half22float2(p01);
            float2 f23 = __half22float2(p23);
            v = make_float4(f01.x, f01.y, f23.x, f23.y);
        }
        *(float4*)&Gs[k][row][q * 4] = v;
    }
    __syncthreads();

    const int lane = tid & 31;
    const int wrp  = tid >> 5;
    const bool act = lane < 28;
    const int q    = act ? lane : 27;
    const bool nzl = (lane > 0);
    const bool nzr = (lane < 27);

    float* ob = out + ((size_t)(b * OO + o) * 8) * HWSZ + h0 * WW + q * 4;

    #pragma unroll
    for (int i = 0; i < 4; i++) {
        const int hl = wrp + i * 8;
        if (hl >= TH) break;
        const int r = hl + 1;

        float4 A  = *(float4*)&Gs[1][r    ][q * 4];
        float4 B0 = *(float4*)&Gs[0][r - 1][q * 4];
        float4 B1 = *(float4*)&Gs[0][r    ][q * 4];
        float4 B2 = *(float4*)&Gs[0][r + 1][q * 4];
        float4 C0 = *(float4*)&Gs[2][r - 1][q * 4];
        float4 C1 = *(float4*)&Gs[2][r    ][q * 4];
        float4 C2 = *(float4*)&Gs[2][r + 1][q * 4];

        float B0l = __shfl_up_sync(0xffffffffu, B0.w, 1);  B0l = nzl ? B0l : 0.f;
        float B1l = __shfl_up_sync(0xffffffffu, B1.w, 1);  B1l = nzl ? B1l : 0.f;
        float B2l = __shfl_up_sync(0xffffffffu, B2.w, 1);  B2l = nzl ? B2l : 0.f;
        float C0l = __shfl_up_sync(0xffffffffu, C0.w, 1);  C0l = nzl ? C0l : 0.f;
        float C1l = __shfl_up_sync(0xffffffffu, C1.w, 1);  C1l = nzl ? C1l : 0.f;
        float C2l = __shfl_up_sync(0xffffffffu, C2.w, 1);  C2l = nzl ? C2l : 0.f;
        float B0r = __shfl_down_sync(0xffffffffu, B0.x, 1); B0r = nzr ? B0r : 0.f;
        float B1r = __shfl_down_sync(0xffffffffu, B1.x, 1); B1r = nzr ? B1r : 0.f;
        float B2r = __shfl_down_sync(0xffffffffu, B2.x, 1); B2r = nzr ? B2r : 0.f;
        float C0r = __shfl_down_sync(0xffffffffu, C0.x, 1); C0r = nzr ? C0r : 0.f;
        float C1r = __shfl_down_sync(0xffffffffu, C1.x, 1); C1r = nzr ? C1r : 0.f;
        float C2r = __shfl_down_sync(0xffffffffu, C2.x, 1); C2r = nzr ? C2r : 0.f;

        if (act) {
            float* op = ob + hl * WW;
            float4 res;
            res.x = A.x + B1l  + C1.y; res.y = A.y + B1.x + C1.z;
            res.z = A.z + B1.y + C1.w; res.w = A.w + B1.z + C1r;
            __stcs((float4*)(op + 0 * HWSZ), res);
            res.x = A.x + B0l  + C2.y; res.y = A.y + B0.x + C2.z;
            res.z = A.z + B0.y + C2.w; res.w = A.w + B0.z + C2r;
            __stcs((float4*)(op + 1 * HWSZ), res);
            res.x = A.x + B0.x + C2.x; res.y = A.y + B0.y + C2.y;
            res.z = A.z + B0.z + C2.z; res.w = A.w + B0.w + C2.w;
            __stcs((float4*)(op + 2 * HWSZ), res);
            res.x = A.x + B0.y + C2l;  res.y = A.y + B0.z + C2.x;
            res.z = A.z + B0.w + C2.y; res.w = A.w + B0r  + C2.z;
            __stcs((float4*)(op + 3 * HWSZ), res);
            res.x = A.x + B1.y + C1l;  res.y = A.y + B1.z + C1.x;
            res.z = A.z + B1.w + C1.y; res.w = A.w + B1r  + C1.z;
            __stcs((float4*)(op + 4 * HWSZ), res);
            res.x = A.x + B2.y + C0l;  res.y = A.y + B2.z + C0.x;
            res.z = A.z + B2.w + C0.y; res.w = A.w + B2r  + C0.z;
            __stcs((float4*)(op + 5 * HWSZ), res);
            res.x = A.x + B2.x + C0.x; res.y = A.y + B2.y + C0.y;
            res.z = A.z + B2.z + C0.z; res.w = A.w + B2.w + C0.w;
            __stcs((float4*)(op + 6 * HWSZ), res);
            res.x = A.x + B2l  + C0.y; res.y = A.y + B2.x + C0.z;
            res.z = A.z + B2.y + C0.w; res.w = A.w + B2.z + C0r;
            __stcs((float4*)(op + 7 * HWSZ), res);
        }
    }
}

// ---------------------------------------------------------------------------
extern "C" void kernel_launch(void* const* d_in, const int* in_sizes, int n_in,
                              void* d_out, int out_size) {
    const float* x = (const float*)d_in[0];       // [16,128,112,112]
    const float* w = (const float*)d_in[1];       // [128,128,3]
    float* out = (float*)d_out;                   // [16,128,8,112,112]

    prep_w<<<(3 * 128 * WPITCH + 255) / 256, 256>>>(w);

    const int dyn_smem = XBYTES + 2 * WTAP;       // 104448 B
    cudaFuncSetAttribute(pass1_mma,
                         cudaFuncAttributeMaxDynamicSharedMemorySize, dyn_smem);
    dim3 g1(HWSZ / NT, BB);                       // (98, 16)
    pass1_mma<<<g1, 256, dyn_smem>>>(x);

    pass2_shift<<<BB * OO * 4, 256>>>(out);
}